// round 3
// baseline (speedup 1.0000x reference)
#include <cuda_runtime.h>
#include <cuda_fp16.h>
#include <cstdint>
#include <cstddef>

// Problem dims
#define BB    64
#define CC    512
#define HWS   784
#define MTOT  (BB * HWS)        // 50176
#define MTILE 128
#define NTILE 256
#define KCH   64                // K chunk
#define NCHNK (CC / KCH)        // 8

// smem: 3 stages x { A[128][72] f16 (18432B) + B[256][72] f16 (36864B) } = 165888
// params at 165888: 5 x 256 f32 = 5120  -> total 171008
// epilogue D-half tile (128 x 129 f32 = 66048B) reuses stage area
#define ROWB     144u
#define ASTAGE   18432u
#define STAGEB   55296u
#define SMPAR    165888u
#define SMTOTAL  171008u
#define TPITCH   129

// ---------------- scratch ----------------
__device__ __half g_a[(size_t)MTOT * CC];   // binarized activations [M][K], +-1 fp16
__device__ __half g_wb[CC * CC];            // sign(W) [N][K], +-1 fp16
__device__ float g_alpha[CC];
__device__ float g_beta2[CC];

// ---------------- helpers ----------------
static __device__ __forceinline__ uint32_t smem_u32(const void* p) {
    uint32_t a;
    asm("{ .reg .u64 t; cvta.to.shared.u64 t, %1; cvt.u32.u64 %0, t; }" : "=r"(a) : "l"(p));
    return a;
}
static __device__ __forceinline__ void cp16(uint32_t s, const void* g) {
    asm volatile("cp.async.cg.shared.global [%0], [%1], 16;" :: "r"(s), "l"(g) : "memory");
}
#define CP_COMMIT() asm volatile("cp.async.commit_group;" ::: "memory")
#define CP_WAIT(n)  asm volatile("cp.async.wait_group %0;" :: "n"(n) : "memory")

static __device__ __forceinline__ void ldsm4(uint32_t* r, uint32_t a) {
    asm volatile("ldmatrix.sync.aligned.m8n8.x4.shared.b16 {%0,%1,%2,%3}, [%4];"
                 : "=r"(r[0]), "=r"(r[1]), "=r"(r[2]), "=r"(r[3]) : "r"(a));
}
static __device__ __forceinline__ void mma_h(uint32_t* c, const uint32_t* a,
                                             uint32_t b0, uint32_t b1) {
    asm volatile(
        "mma.sync.aligned.m16n8k16.row.col.f16.f16.f16.f16 "
        "{%0,%1}, {%2,%3,%4,%5}, {%6,%7}, {%0,%1};"
        : "+r"(c[0]), "+r"(c[1])
        : "r"(a[0]), "r"(a[1]), "r"(a[2]), "r"(a[3]), "r"(b0), "r"(b1));
}

// ---------------- kernel 1: epilogue constants ----------------
__global__ void prep_kernel(const float* __restrict__ W, const float* __restrict__ gam,
                            const float* __restrict__ bet, const float* __restrict__ mea,
                            const float* __restrict__ var) {
    int wid = threadIdx.x >> 5, lane = threadIdx.x & 31;
    int o = blockIdx.x * 8 + wid;
    const float* wr = W + (size_t)o * CC;
    float s = 0.f;
    #pragma unroll
    for (int j = 0; j < 16; j++) s += fabsf(wr[lane + j * 32]);
    #pragma unroll
    for (int off = 16; off > 0; off >>= 1) s += __shfl_xor_sync(0xffffffffu, s, off);
    if (lane == 0) {
        float scale = s * (1.0f / 512.0f);
        float A = gam[o] * rsqrtf(var[o] + 1e-5f);
        g_alpha[o] = A * scale;
        g_beta2[o] = bet[o] - A * mea[o];
    }
}

// ---------------- kernel 2: Wb = sign(W) as fp16 (+-1) ----------------
__global__ void sign_w_kernel(const float* __restrict__ W) {
    int i = blockIdx.x * blockDim.x + threadIdx.x;
    float2 v = reinterpret_cast<const float2*>(W)[i];
    uint32_t p = ((v.x >= 0.f) ? 0x3C00u : 0xBC00u) |
                 (((v.y >= 0.f) ? 0x3C00u : 0xBC00u) << 16);
    reinterpret_cast<uint32_t*>(g_wb)[i] = p;
}

// ---------------- kernel 3: binarize x + transpose NCHW -> [M][K] fp16 ----------------
__global__ void binarize_kernel(const float* __restrict__ x, const float* __restrict__ rb) {
    __shared__ unsigned short ts[64][66];
    int b   = blockIdx.z;
    int k0  = blockIdx.y * 64;
    int hw0 = blockIdx.x * 64;
    int tid = threadIdx.x;

    #pragma unroll
    for (int i = 0; i < 16; i++) {
        int idx = tid + i * 256;
        int cc = idx >> 6, hh = idx & 63;
        int hw = hw0 + hh;
        if (hw < HWS) {
            float v = x[(size_t)((b << 9) + k0 + cc) * HWS + hw] + rb[k0 + cc];
            ts[hh][cc] = (v >= 0.f) ? 0x3C00 : 0xBC00;
        }
    }
    __syncthreads();
    #pragma unroll
    for (int i = 0; i < 8; i++) {
        int j = tid + i * 256;
        int hh = j >> 5, c2 = (j & 31) * 2;
        int hw = hw0 + hh;
        if (hw < HWS) {
            uint32_t v = (uint32_t)ts[hh][c2] | ((uint32_t)ts[hh][c2 + 1] << 16);
            *reinterpret_cast<uint32_t*>(&g_a[(size_t)(b * HWS + hw) * CC + k0 + c2]) = v;
        }
    }
}

// ---------------- kernel 4: fp16-accum mma GEMM + fused epilogue ----------------
__global__ void __launch_bounds__(256, 1)
gemm_kernel(const float* __restrict__ x, const float* __restrict__ slope,
            const float* __restrict__ shift, const float* __restrict__ pbias,
            float* __restrict__ out)
{
    extern __shared__ char smem[];
    const uint32_t sb = smem_u32(smem);
    const int tid = threadIdx.x, wid = tid >> 5, lane = tid & 31;
    const int m0 = blockIdx.y * MTILE;
    const int n0 = blockIdx.x * NTILE;

    float* alphaS = reinterpret_cast<float*>(smem + SMPAR);
    float* betaS  = alphaS + 256;
    float* slopeS = alphaS + 512;
    float* shiftS = alphaS + 768;
    float* pbiasS = alphaS + 1024;
    alphaS[tid] = g_alpha[n0 + tid];
    betaS[tid]  = g_beta2[n0 + tid];
    slopeS[tid] = slope[n0 + tid];
    shiftS[tid] = shift[n0 + tid];
    pbiasS[tid] = pbias[n0 + tid];

    const int ldrow = tid >> 3;           // 0..31
    const int ldseg = tid & 7;            // 16B segment (8 per 128B k-chunk row)

    // stage loader: A[128 rows] + B[256 rows] of 64-k fp16
    auto load_stage = [&](int c, int st) {
        const uint32_t so = sb + (uint32_t)st * STAGEB;
        const char* ga = (const char*)g_a  + ((size_t)m0 * CC + c * KCH) * 2 + ldseg * 16;
        const char* gb = (const char*)g_wb + ((size_t)n0 * CC + c * KCH) * 2 + ldseg * 16;
        #pragma unroll
        for (int j = 0; j < 4; j++) {
            int row = ldrow + j * 32;
            cp16(so + row * ROWB + ldseg * 16, ga + (size_t)row * (CC * 2));
        }
        #pragma unroll
        for (int j = 0; j < 8; j++) {
            int row = ldrow + j * 32;
            cp16(so + ASTAGE + row * ROWB + ldseg * 16, gb + (size_t)row * (CC * 2));
        }
        CP_COMMIT();
    };

    load_stage(0, 0);
    load_stage(1, 1);

    uint32_t acc[4][8][2] = {};           // [mt][nt][2] packed f16x2
    const int mw = (wid >> 2) * 64;       // warp row: 0 / 64
    const int nw = (wid & 3) * 64;        // warp col: 0/64/128/192

    const int rowSel = (lane & 7) + ((lane >> 3) & 1) * 8;
    const int colSel = ((lane >> 4) & 1) * 8;

    #pragma unroll
    for (int c = 0; c < NCHNK; c++) {
        if (c == NCHNK - 1) { CP_WAIT(0); } else { CP_WAIT(1); }
        __syncthreads();
        if (c + 2 < NCHNK) load_stage(c + 2, (c + 2) % 3);

        const uint32_t aBase = sb + (uint32_t)(c % 3) * STAGEB;
        const uint32_t bBase = aBase + ASTAGE;
        #pragma unroll
        for (int ks = 0; ks < 4; ks++) {
            uint32_t af[4][4], bf[4][4];
            #pragma unroll
            for (int mt = 0; mt < 4; mt++) {
                int r = mw + mt * 16 + rowSel;
                ldsm4(af[mt], aBase + r * ROWB + (ks * 16 + colSel) * 2);
            }
            #pragma unroll
            for (int nt2 = 0; nt2 < 4; nt2++) {
                int r = nw + nt2 * 16 + rowSel;
                ldsm4(bf[nt2], bBase + r * ROWB + (ks * 16 + colSel) * 2);
            }
            #pragma unroll
            for (int mt = 0; mt < 4; mt++) {
                #pragma unroll
                for (int nt2 = 0; nt2 < 4; nt2++) {
                    mma_h(acc[mt][2 * nt2],     af[mt], bf[nt2][0], bf[nt2][2]);
                    mma_h(acc[mt][2 * nt2 + 1], af[mt], bf[nt2][1], bf[nt2][3]);
                }
            }
        }
        __syncthreads();
    }

    // ---- epilogue in two 128-col halves, staged through smem ----
    float* tile = reinterpret_cast<float*>(smem);
    const int dr = lane >> 2;
    const int dc = (lane & 3) * 2;
    const int myhalf = (wid & 3) >> 1;          // warp cols 0,1 -> half0; 2,3 -> half1
    const int nlb = (wid & 1) * 64;             // col base within the half

    #pragma unroll
    for (int h = 0; h < 2; h++) {
        if (myhalf == h) {
            #pragma unroll
            for (int mt = 0; mt < 4; mt++) {
                #pragma unroll
                for (int nt = 0; nt < 8; nt++) {
                    int r = mw + mt * 16 + dr;
                    int c2 = nlb + nt * 8 + dc;
                    float2 lo = __half22float2(*reinterpret_cast<__half2*>(&acc[mt][nt][0]));
                    float2 hi = __half22float2(*reinterpret_cast<__half2*>(&acc[mt][nt][1]));
                    tile[r * TPITCH + c2]           = lo.x;
                    tile[r * TPITCH + c2 + 1]       = lo.y;
                    tile[(r + 8) * TPITCH + c2]     = hi.x;
                    tile[(r + 8) * TPITCH + c2 + 1] = hi.y;
                }
            }
        }
        __syncthreads();

        #pragma unroll 4
        for (int g = 0; g < 16; g++) {
            const int nl = wid + 8 * g;          // 0..127
            const int p = h * 128 + nl;
            const int n = n0 + p;
            const float al = alphaS[p], be = betaS[p];
            const float sl = slopeS[p], sh = shiftS[p], pb = pbiasS[p];
            #pragma unroll
            for (int j = 0; j < 4; j++) {
                int ml = lane + 32 * j;
                int m = m0 + ml;
                int b = m / HWS;
                int hw = m - b * HWS;
                size_t gi = ((size_t)(b * CC + n)) * HWS + hw;
                float raw = tile[ml * TPITCH + nl];
                float sv = fmaf(al, raw, be) + x[gi];
                float t = sv - sh;
                out[gi] = ((t > 0.f) ? t : sl * t) + pb;
            }
        }
        __syncthreads();
    }
}

// ---------------- launch ----------------
extern "C" void kernel_launch(void* const* d_in, const int* in_sizes, int n_in,
                              void* d_out, int out_size) {
    const float* x   = (const float*)d_in[0];
    const float* rb  = (const float*)d_in[1];
    const float* W   = (const float*)d_in[2];
    const float* gam = (const float*)d_in[3];
    const float* bet = (const float*)d_in[4];
    const float* mea = (const float*)d_in[5];
    const float* var = (const float*)d_in[6];
    const float* slo = (const float*)d_in[7];
    const float* shi = (const float*)d_in[8];
    const float* pbi = (const float*)d_in[9];
    float* out = (float*)d_out;

    cudaFuncSetAttribute(gemm_kernel, cudaFuncAttributeMaxDynamicSharedMemorySize, SMTOTAL);

    prep_kernel<<<64, 256>>>(W, gam, bet, mea, var);
    sign_w_kernel<<<512, 256>>>(W);
    binarize_kernel<<<dim3(13, 8, 64), 256>>>(x, rb);
    gemm_kernel<<<dim3(2, MTOT / MTILE), 256, SMTOTAL>>>(x, slo, shi, pbi, out);
}

// round 4
// speedup vs baseline: 1.3043x; 1.3043x over previous
#include <cuda_runtime.h>
#include <cuda_fp16.h>
#include <cstdint>
#include <cstddef>

// Problem dims
#define BB    64
#define CC    512
#define HWS   784
#define MTOT  (BB * HWS)        // 50176
#define MTILE 128
#define NTILE 256
#define KCH   64                // K chunk
#define NCHNK (CC / KCH)        // 8

// smem: 2 stages x { A[128][128B] 16384 + B[256][128B] 32768 } = 98304 (swizzled, no pad)
// params at 98304: 5 x 256 f32 = 5120 -> total 103424  (2 CTAs/SM)
// epilogue D-half tile (128 x 129 f32 = 66048B) reuses stage area
#define ASZ      16384u
#define STAGEB   49152u
#define SMPAR    98304u
#define SMTOTAL  103424u
#define TPITCH   129

// ---------------- scratch ----------------
__device__ __half g_a[(size_t)MTOT * CC];   // binarized activations [M][K], +-1 fp16
__device__ __half g_wb[CC * CC];            // sign(W) [N][K], +-1 fp16
__device__ float g_alpha[CC];
__device__ float g_beta2[CC];

// ---------------- helpers ----------------
static __device__ __forceinline__ uint32_t smem_u32(const void* p) {
    uint32_t a;
    asm("{ .reg .u64 t; cvta.to.shared.u64 t, %1; cvt.u32.u64 %0, t; }" : "=r"(a) : "l"(p));
    return a;
}
static __device__ __forceinline__ void cp16(uint32_t s, const void* g) {
    asm volatile("cp.async.cg.shared.global [%0], [%1], 16;" :: "r"(s), "l"(g) : "memory");
}
#define CP_COMMIT() asm volatile("cp.async.commit_group;" ::: "memory")
#define CP_WAIT(n)  asm volatile("cp.async.wait_group %0;" :: "n"(n) : "memory")

static __device__ __forceinline__ void ldsm4(uint32_t* r, uint32_t a) {
    asm volatile("ldmatrix.sync.aligned.m8n8.x4.shared.b16 {%0,%1,%2,%3}, [%4];"
                 : "=r"(r[0]), "=r"(r[1]), "=r"(r[2]), "=r"(r[3]) : "r"(a));
}
static __device__ __forceinline__ void mma_h(uint32_t* c, const uint32_t* a,
                                             uint32_t b0, uint32_t b1) {
    asm volatile(
        "mma.sync.aligned.m16n8k16.row.col.f16.f16.f16.f16 "
        "{%0,%1}, {%2,%3,%4,%5}, {%6,%7}, {%0,%1};"
        : "+r"(c[0]), "+r"(c[1])
        : "r"(a[0]), "r"(a[1]), "r"(a[2]), "r"(a[3]), "r"(b0), "r"(b1));
}
// swizzled smem offset for (row, 16B-seg) within a 128B-row matrix
static __device__ __forceinline__ uint32_t swz(int row, int seg) {
    return (uint32_t)(row * 128 + ((seg ^ (row & 7)) << 4));
}

// ---------------- kernel 1: epilogue constants ----------------
__global__ void prep_kernel(const float* __restrict__ W, const float* __restrict__ gam,
                            const float* __restrict__ bet, const float* __restrict__ mea,
                            const float* __restrict__ var) {
    int wid = threadIdx.x >> 5, lane = threadIdx.x & 31;
    int o = blockIdx.x * 8 + wid;
    const float* wr = W + (size_t)o * CC;
    float s = 0.f;
    #pragma unroll
    for (int j = 0; j < 16; j++) s += fabsf(wr[lane + j * 32]);
    #pragma unroll
    for (int off = 16; off > 0; off >>= 1) s += __shfl_xor_sync(0xffffffffu, s, off);
    if (lane == 0) {
        float scale = s * (1.0f / 512.0f);
        float A = gam[o] * rsqrtf(var[o] + 1e-5f);
        g_alpha[o] = A * scale;
        g_beta2[o] = bet[o] - A * mea[o];
    }
}

// ---------------- kernel 2: Wb = sign(W) as fp16 (+-1) ----------------
__global__ void sign_w_kernel(const float* __restrict__ W) {
    int i = blockIdx.x * blockDim.x + threadIdx.x;
    float2 v = reinterpret_cast<const float2*>(W)[i];
    uint32_t p = ((v.x >= 0.f) ? 0x3C00u : 0xBC00u) |
                 (((v.y >= 0.f) ? 0x3C00u : 0xBC00u) << 16);
    reinterpret_cast<uint32_t*>(g_wb)[i] = p;
}

// ---------------- kernel 3: binarize x + transpose NCHW -> [M][K] fp16 ----------------
// 64hw x 64c tile; float4 loads, uint4 coalesced stores.
__global__ void binarize_kernel(const float* __restrict__ x, const float* __restrict__ rb) {
    __shared__ unsigned short ts[64][72];   // [hw][c], 144B pitch (16B aligned)
    const int b   = blockIdx.z;
    const int k0  = blockIdx.y * 64;
    const int hw0 = blockIdx.x * 64;
    const int tid = threadIdx.x;

    #pragma unroll
    for (int i = 0; i < 4; i++) {
        int idx = tid + i * 256;            // 1024 tasks
        int cc = idx >> 4;                  // 0..63
        int hs = idx & 15;                  // 16 float4 segs over hw
        int hw = hw0 + hs * 4;
        float rbv = rb[k0 + cc];
        const float* xp = x + (size_t)((b << 9) + k0 + cc) * HWS + hw;
        if (hw + 3 < HWS) {
            float4 v = *reinterpret_cast<const float4*>(xp);
            ts[hs * 4 + 0][cc] = (v.x + rbv >= 0.f) ? 0x3C00 : 0xBC00;
            ts[hs * 4 + 1][cc] = (v.y + rbv >= 0.f) ? 0x3C00 : 0xBC00;
            ts[hs * 4 + 2][cc] = (v.z + rbv >= 0.f) ? 0x3C00 : 0xBC00;
            ts[hs * 4 + 3][cc] = (v.w + rbv >= 0.f) ? 0x3C00 : 0xBC00;
        } else {
            #pragma unroll
            for (int e = 0; e < 4; e++)
                if (hw + e < HWS)
                    ts[hs * 4 + e][cc] = (xp[e] + rbv >= 0.f) ? 0x3C00 : 0xBC00;
        }
    }
    __syncthreads();
    #pragma unroll
    for (int i = 0; i < 2; i++) {
        int idx = tid + i * 256;            // 512 tasks
        int row = idx >> 3;                 // 0..63
        int seg = idx & 7;                  // 16B seg
        int hw = hw0 + row;
        if (hw < HWS) {
            uint4 v = *reinterpret_cast<const uint4*>(&ts[row][seg * 8]);
            *reinterpret_cast<uint4*>(
                &g_a[(size_t)(b * HWS + hw) * CC + k0 + seg * 8]) = v;
        }
    }
}

// ---------------- kernel 4: fp16-accum mma GEMM + fused epilogue ----------------
__global__ void __launch_bounds__(256, 2)
gemm_kernel(const float* __restrict__ x, const float* __restrict__ slope,
            const float* __restrict__ shift, const float* __restrict__ pbias,
            float* __restrict__ out)
{
    extern __shared__ char smem[];
    const uint32_t sb = smem_u32(smem);
    const int tid = threadIdx.x, wid = tid >> 5, lane = tid & 31;
    const int m0 = blockIdx.y * MTILE;
    const int n0 = blockIdx.x * NTILE;

    float* alphaS = reinterpret_cast<float*>(smem + SMPAR);
    float* betaS  = alphaS + 256;
    float* slopeS = alphaS + 512;
    float* shiftS = alphaS + 768;
    float* pbiasS = alphaS + 1024;
    alphaS[tid] = g_alpha[n0 + tid];
    betaS[tid]  = g_beta2[n0 + tid];
    slopeS[tid] = slope[n0 + tid];
    shiftS[tid] = shift[n0 + tid];
    pbiasS[tid] = pbias[n0 + tid];

    const int ldrow = tid >> 3;           // 0..31
    const int ldseg = tid & 7;            // 16B seg within 128B k-chunk row

    auto load_stage = [&](int c, int st) {
        const uint32_t so = sb + (uint32_t)st * STAGEB;
        const char* ga = (const char*)g_a  + ((size_t)m0 * CC + c * KCH) * 2;
        const char* gb = (const char*)g_wb + ((size_t)n0 * CC + c * KCH) * 2;
        #pragma unroll
        for (int j = 0; j < 4; j++) {
            int row = ldrow + j * 32;
            cp16(so + swz(row, ldseg), ga + (size_t)row * (CC * 2) + ldseg * 16);
        }
        #pragma unroll
        for (int j = 0; j < 8; j++) {
            int row = ldrow + j * 32;
            cp16(so + ASZ + swz(row, ldseg), gb + (size_t)row * (CC * 2) + ldseg * 16);
        }
        CP_COMMIT();
    };

    load_stage(0, 0);

    uint32_t acc[4][8][2] = {};           // warp 64x64, f16x2 packed acc
    const int mw = (wid >> 2) * 64;       // warp row: 0/64
    const int nw = (wid & 3) * 64;        // warp col: 0/64/128/192

    const int rowSel = (lane & 7) + ((lane >> 3) & 1) * 8;
    const int segHi  = (lane >> 4) & 1;   // k 16B-seg selector within k16

    #pragma unroll
    for (int c = 0; c < NCHNK; c++) {
        if (c + 1 < NCHNK) { load_stage(c + 1, (c + 1) & 1); CP_WAIT(1); }
        else               { CP_WAIT(0); }
        __syncthreads();

        const uint32_t aBase = sb + (uint32_t)(c & 1) * STAGEB;
        const uint32_t bBase = aBase + ASZ;
        #pragma unroll
        for (int ks = 0; ks < 4; ks++) {
            const int kseg = ks * 2 + segHi;
            uint32_t af[4][4], bf[4][4];
            #pragma unroll
            for (int mt = 0; mt < 4; mt++) {
                int r = mw + mt * 16 + rowSel;
                ldsm4(af[mt], aBase + swz(r, kseg));
            }
            #pragma unroll
            for (int nt = 0; nt < 4; nt++) {
                int r = nw + nt * 16 + rowSel;
                ldsm4(bf[nt], bBase + swz(r, kseg));
            }
            #pragma unroll
            for (int mt = 0; mt < 4; mt++) {
                #pragma unroll
                for (int nt = 0; nt < 4; nt++) {
                    mma_h(acc[mt][2 * nt],     af[mt], bf[nt][0], bf[nt][2]);
                    mma_h(acc[mt][2 * nt + 1], af[mt], bf[nt][1], bf[nt][3]);
                }
            }
        }
        __syncthreads();
    }

    // ---- epilogue: two 128-col halves staged through smem ----
    float* tile = reinterpret_cast<float*>(smem);
    const int dr = lane >> 2;
    const int dc = (lane & 3) * 2;
    const int myhalf = (wid & 3) >> 1;
    const int nlb = (wid & 1) * 64;

    #pragma unroll
    for (int h = 0; h < 2; h++) {
        if (myhalf == h) {
            #pragma unroll
            for (int mt = 0; mt < 4; mt++) {
                #pragma unroll
                for (int nt = 0; nt < 8; nt++) {
                    int r = mw + mt * 16 + dr;
                    int c2 = nlb + nt * 8 + dc;
                    float2 lo = __half22float2(*reinterpret_cast<__half2*>(&acc[mt][nt][0]));
                    float2 hi = __half22float2(*reinterpret_cast<__half2*>(&acc[mt][nt][1]));
                    tile[r * TPITCH + c2]           = lo.x;
                    tile[r * TPITCH + c2 + 1]       = lo.y;
                    tile[(r + 8) * TPITCH + c2]     = hi.x;
                    tile[(r + 8) * TPITCH + c2 + 1] = hi.y;
                }
            }
        }
        __syncthreads();

        #pragma unroll 4
        for (int g = 0; g < 16; g++) {
            const int nl = wid + 8 * g;          // 0..127
            const int p = h * 128 + nl;
            const int n = n0 + p;
            const float al = alphaS[p], be = betaS[p];
            const float sl = slopeS[p], sh = shiftS[p], pb = pbiasS[p];
            #pragma unroll
            for (int j = 0; j < 4; j++) {
                int ml = lane + 32 * j;
                int m = m0 + ml;
                int b = m / HWS;
                int hw = m - b * HWS;
                size_t gi = ((size_t)(b * CC + n)) * HWS + hw;
                float raw = tile[ml * TPITCH + nl];
                float sv = fmaf(al, raw, be) + x[gi];
                float t = sv - sh;
                out[gi] = ((t > 0.f) ? t : sl * t) + pb;
            }
        }
        __syncthreads();
    }
}

// ---------------- launch ----------------
extern "C" void kernel_launch(void* const* d_in, const int* in_sizes, int n_in,
                              void* d_out, int out_size) {
    const float* x   = (const float*)d_in[0];
    const float* rb  = (const float*)d_in[1];
    const float* W   = (const float*)d_in[2];
    const float* gam = (const float*)d_in[3];
    const float* bet = (const float*)d_in[4];
    const float* mea = (const float*)d_in[5];
    const float* var = (const float*)d_in[6];
    const float* slo = (const float*)d_in[7];
    const float* shi = (const float*)d_in[8];
    const float* pbi = (const float*)d_in[9];
    float* out = (float*)d_out;

    cudaFuncSetAttribute(gemm_kernel, cudaFuncAttributeMaxDynamicSharedMemorySize, SMTOTAL);

    prep_kernel<<<64, 256>>>(W, gam, bet, mea, var);
    sign_w_kernel<<<512, 256>>>(W);
    binarize_kernel<<<dim3(13, 8, 64), 256>>>(x, rb);
    gemm_kernel<<<dim3(2, MTOT / MTILE), 256, SMTOTAL>>>(x, slo, shi, pbi, out);
}